// round 15
// baseline (speedup 1.0000x reference)
#include <cuda_runtime.h>
#include <cstdint>
#include <math.h>

// PatchRepulsionLoss: pcs [8192, 2048, 3] f32 -> scalar f32
// B=8192, P=32 patches, n=64 pts/patch, N_SIGMA=1
// loss = sum_b sum_{i<=j} || relu(std_i+std_j - |mean_i-mean_j|) ||_2 / (528*B)
//
// Pair identity: std_i+std_j - |m_i-m_j| = min(hi_j - lo_i, hi_i - lo_j).
//
// 512-thread CTAs, 2 batches per CTA in independent warp groups. TMA issue
// moved AHEAD of the init-visibility barrier: lane 0 of warps 0-3 inits its
// own mbarrier and immediately issues its 12KB chunk (same-thread ordering);
// the __syncthreads that publishes inits to consumers overlaps the transfer.
// PDL overlaps the zero kernel with the main grid.

#define NPATCH 32
#define NBATCH 8192
#define GRIDSZ (NBATCH / 2)
#define NTHREADS 512
#define CHUNK_BYTES 12288            // 16 patches
#define BATCH_BYTES (2 * CHUNK_BYTES)

__global__ void prl_zero_kernel(float* out) {
    out[0] = 0.0f;
    cudaTriggerProgrammaticLaunchCompletion();
}

__device__ __forceinline__ uint32_t smem_u32(const void* p) {
    uint32_t a;
    asm("{ .reg .u64 t; cvta.to.shared.u64 t, %1; cvt.u32.u64 %0, t; }"
        : "=r"(a) : "l"(p));
    return a;
}

__device__ __forceinline__ void bulk_copy(uint32_t dst, const void* src,
                                          uint32_t bytes, uint32_t mbar) {
    asm volatile("mbarrier.arrive.expect_tx.shared.b64 _, [%0], %1;"
                 :: "r"(mbar), "r"(bytes) : "memory");
    asm volatile(
        "cp.async.bulk.shared::cta.global.mbarrier::complete_tx::bytes "
        "[%0], [%1], %2, [%3];"
        :: "r"(dst), "l"(src), "r"(bytes), "r"(mbar) : "memory");
}

__device__ __forceinline__ void mbar_wait0(uint32_t mbar) {
    uint32_t done;
    asm volatile(
        "{\n\t.reg .pred p;\n\t"
        "mbarrier.try_wait.parity.acquire.cta.shared::cta.b64 p, [%1], 0;\n\t"
        "selp.b32 %0, 1, 0, p;\n\t}"
        : "=r"(done) : "r"(mbar) : "memory");
    if (!done) {
        asm volatile(
            "{\n\t.reg .pred P1;\n\t"
            "WL_%=:\n\t"
            "mbarrier.try_wait.parity.acquire.cta.shared::cta.b64 P1, [%0], 0, 0x989680;\n\t"
            "@P1 bra.uni WD_%=;\n\t"
            "bra.uni WL_%=;\n\t"
            "WD_%=:\n\t}"
            :: "r"(mbar) : "memory");
    }
}

__device__ __forceinline__ float sqrt_approx(float x) {
    float r;
    asm("sqrt.approx.f32 %0, %1;" : "=f"(r) : "f"(x));
    return r;
}

#define PACK2(out, lo, hi) \
    asm("mov.b64 %0, {%1, %2};" : "=l"(out) : "f"(lo), "f"(hi))
#define UNPACK2(lo, hi, in) \
    asm("mov.b64 {%0, %1}, %2;" : "=f"(lo), "=f"(hi) : "l"(in))

__global__ void __launch_bounds__(NTHREADS, 4)
prl_main_kernel(const float* __restrict__ pcs, float* __restrict__ out) {
    __shared__ alignas(128) float4 sbuf[3072];          // 48 KB: A at 0, B at 1536
    __shared__ alignas(8) uint64_t mbar[4];             // A0 A1 B0 B1
    __shared__ uint64_t s_lo01[2][NPATCH];              // per group packed {lo0,lo1}
    __shared__ uint64_t s_hi01[2][NPATCH];
    __shared__ float s_lo2[2][NPATCH];
    __shared__ float s_hi2[2][NPATCH];
    __shared__ float s_part[16];

    const int tid = threadIdx.x;
    const int lane = tid & 31;
    const int warp = tid >> 5;
    const int grp = tid >> 8;           // 0: batch A (warps 0-7), 1: batch B
    const int gw = warp & 7;            // warp index within group
    const int gt = tid & 255;           // thread index within group
    const int half = gt >> 7;           // group-warps 0-3 -> chunk0, 4-7 -> chunk1
    const int tl = gt & 127;
    const uint32_t sbase = smem_u32(sbuf);
    const uint32_t mbase = smem_u32(mbar);
    const char* src = reinterpret_cast<const char*>(pcs) +
                      (size_t)blockIdx.x * (2 * BATCH_BYTES);

    // Earliest-possible TMA: lane 0 of warps 0-3 inits ITS OWN mbarrier and
    // immediately issues its 12KB chunk (init -> expect_tx same-thread
    // ordered). Chunks 0,1 = batch A; 2,3 = batch B.
    if (warp < 4 && lane == 0) {
        asm volatile("mbarrier.init.shared.b64 [%0], 1;"
                     :: "r"(mbase + 8 * warp) : "memory");
        bulk_copy(sbase + (uint32_t)warp * CHUNK_BYTES,
                  src + (size_t)warp * CHUNK_BYTES,
                  CHUNK_BYTES, mbase + 8 * warp);
    }
    __syncthreads();   // publishes inits to consumers; TMA already in flight

    mbar_wait0(mbase + 8 * (2 * grp + half));

    // ---- Stats: thread owns f4[6*tl .. 6*tl+5] of its group's chunk (24
    // consecutive floats, phase 0). Bank-conflict fix: delta lanes swap
    // j <-> j+3 (+/-48B); (j+3)%3 == j%3 so the dim phase is preserved.
    const int sd = ((lane >> 2) & 1) ? 48 : 0;
    uint64_t S01 = 0, S20 = 0, S12 = 0;
    uint64_t Q01 = 0, Q20 = 0, Q12 = 0;
    const uint32_t tbase = sbase + (uint32_t)(2 * grp + half) * CHUNK_BYTES +
                           (uint32_t)tl * 96;

#pragma unroll
    for (int j = 0; j < 6; j++) {
        const int off = 16 * j + ((j < 3) ? sd : -sd);
        uint64_t plo, phi;   // plo=(e0,e1), phi=(e2,e3); f4 phase = j mod 3
        asm("ld.shared.v2.b64 {%0,%1}, [%2];"
            : "=l"(plo), "=l"(phi) : "r"(tbase + (uint32_t)off));
        if (j % 3 == 0) {      // pairs (0,1),(2,0)
            asm("add.rn.f32x2 %0,%0,%1;" : "+l"(S01) : "l"(plo));
            asm("add.rn.f32x2 %0,%0,%1;" : "+l"(S20) : "l"(phi));
            asm("fma.rn.f32x2 %0,%1,%1,%0;" : "+l"(Q01) : "l"(plo));
            asm("fma.rn.f32x2 %0,%1,%1,%0;" : "+l"(Q20) : "l"(phi));
        } else if (j % 3 == 1) { // pairs (1,2),(0,1)
            asm("add.rn.f32x2 %0,%0,%1;" : "+l"(S12) : "l"(plo));
            asm("add.rn.f32x2 %0,%0,%1;" : "+l"(S01) : "l"(phi));
            asm("fma.rn.f32x2 %0,%1,%1,%0;" : "+l"(Q12) : "l"(plo));
            asm("fma.rn.f32x2 %0,%1,%1,%0;" : "+l"(Q01) : "l"(phi));
        } else {                 // pairs (2,0),(1,2)
            asm("add.rn.f32x2 %0,%0,%1;" : "+l"(S20) : "l"(plo));
            asm("add.rn.f32x2 %0,%0,%1;" : "+l"(S12) : "l"(phi));
            asm("fma.rn.f32x2 %0,%1,%1,%0;" : "+l"(Q20) : "l"(plo));
            asm("fma.rn.f32x2 %0,%1,%1,%0;" : "+l"(Q12) : "l"(phi));
        }
    }

    // combine: s_d0 = S01.lo+S20.hi, s_d1 = S01.hi+S12.lo, s_d2 = S20.lo+S12.hi
    float a0l, a0h, a1l, a1h, a2l, a2h;
    UNPACK2(a0l, a0h, S01); UNPACK2(a1l, a1h, S20); UNPACK2(a2l, a2h, S12);
    float s0 = a0l + a1h, s1 = a0h + a2l, s2 = a1l + a2h;
    UNPACK2(a0l, a0h, Q01); UNPACK2(a1l, a1h, Q20); UNPACK2(a2l, a2h, Q12);
    float q0 = a0l + a1h, q1 = a0h + a2l, q2 = a1l + a2h;

    // 8-lane group reduce (threads 8p..8p+7 of the chunk own patch p)
#pragma unroll
    for (int off = 4; off; off >>= 1) {
        s0 += __shfl_xor_sync(0xFFFFFFFFu, s0, off);
        s1 += __shfl_xor_sync(0xFFFFFFFFu, s1, off);
        s2 += __shfl_xor_sync(0xFFFFFFFFu, s2, off);
        q0 += __shfl_xor_sync(0xFFFFFFFFu, q0, off);
        q1 += __shfl_xor_sync(0xFFFFFFFFu, q1, off);
        q2 += __shfl_xor_sync(0xFFFFFFFFu, q2, off);
    }
    if ((tl & 7) == 0) {
        const int gp = half * 16 + (tl >> 3);
        const float inv_n = 1.0f / 64.0f;
        const float inv_nm1 = 1.0f / 63.0f;
        float m0 = s0 * inv_n, m1 = s1 * inv_n, m2 = s2 * inv_n;
        float sd0 = sqrt_approx(fmaxf((q0 - s0 * m0) * inv_nm1, 0.0f));
        float sd1 = sqrt_approx(fmaxf((q1 - s1 * m1) * inv_nm1, 0.0f));
        float sd2 = sqrt_approx(fmaxf((q2 - s2 * m2) * inv_nm1, 0.0f));
        uint64_t t;
        PACK2(t, m0 - sd0, m1 - sd1); s_lo01[grp][gp] = t;
        PACK2(t, m0 + sd0, m1 + sd1); s_hi01[grp][gp] = t;
        s_lo2[grp][gp] = m2 - sd2;
        s_hi2[grp][gp] = m2 + sd2;
    }
    // group-scoped barrier: batch A warps sync on bar 1, batch B on bar 2
    asm volatile("bar.sync %0, 256;" :: "r"(grp + 1) : "memory");

    // ---- Pair phase: full 32x32 symmetric; upper-tri incl diag =
    // 0.5*full + 0.5*diag -> weight 0.5 off-diag, 1.0 on diag.
    const uint64_t jlo01 = s_lo01[grp][lane];
    const uint64_t jhi01 = s_hi01[grp][lane];
    const float jlo2 = s_lo2[grp][lane];
    const float jhi2 = s_hi2[grp][lane];

    float local = 0.0f;
#pragma unroll
    for (int k = 0; k < 4; k++) {
        const int i = gw + 8 * k;            // uniform within warp
        const uint64_t ilo01 = s_lo01[grp][i];
        const uint64_t ihi01 = s_hi01[grp][i];
        const float ilo2 = s_lo2[grp][i];
        const float ihi2 = s_hi2[grp][i];
        uint64_t dA, dB;                      // packed (ihi-jlo), (jhi-ilo)
        asm("sub.rn.f32x2 %0,%1,%2;" : "=l"(dA) : "l"(ihi01), "l"(jlo01));
        asm("sub.rn.f32x2 %0,%1,%2;" : "=l"(dB) : "l"(jhi01), "l"(ilo01));
        float dA0, dA1, dB0, dB1;
        UNPACK2(dA0, dA1, dA); UNPACK2(dB0, dB1, dB);
        float r0 = fmaxf(fminf(dA0, dB0), 0.0f);
        float r1 = fmaxf(fminf(dA1, dB1), 0.0f);
        float r2 = fmaxf(fminf(ihi2 - jlo2, jhi2 - ilo2), 0.0f);
        float acc = fmaf(r0, r0, fmaf(r1, r1, r2 * r2));
        float nrm = sqrt_approx(acc);
        local += (i == lane) ? nrm : 0.5f * nrm;
    }

    // ---- Joint block reduce (16 warps) + single fire-and-forget atomic ----
#pragma unroll
    for (int off = 16; off; off >>= 1)
        local += __shfl_xor_sync(0xFFFFFFFFu, local, off);
    if (lane == 0) s_part[warp] = local;
    __syncthreads();
    if (warp == 0) {
        float v = (lane < 16) ? s_part[lane] : 0.0f;
#pragma unroll
        for (int off = 8; off; off >>= 1)
            v += __shfl_xor_sync(0xFFFFFFFFu, v, off);
        if (lane == 0) {
            cudaGridDependencySynchronize();   // PDL gate on zero kernel
            const float scale = 1.0f / (528.0f * (float)NBATCH);
            atomicAdd(out, v * scale);
        }
    }
}

extern "C" void kernel_launch(void* const* d_in, const int* in_sizes, int n_in,
                              void* d_out, int out_size) {
    const float* pcs = (const float*)d_in[0];
    float* out = (float*)d_out;

    prl_zero_kernel<<<1, 1>>>(out);

    cudaLaunchConfig_t cfg = {};
    cfg.gridDim = dim3(GRIDSZ, 1, 1);
    cfg.blockDim = dim3(NTHREADS, 1, 1);
    cfg.dynamicSmemBytes = 0;
    cfg.stream = 0;
    cudaLaunchAttribute attr[1];
    attr[0].id = cudaLaunchAttributeProgrammaticStreamSerialization;
    attr[0].val.programmaticStreamSerializationAllowed = 1;
    cfg.attrs = attr;
    cfg.numAttrs = 1;
    cudaLaunchKernelEx(&cfg, prl_main_kernel, pcs, out);
}